// round 12
// baseline (speedup 1.0000x reference)
#include <cuda_runtime.h>
#include <math.h>

#define NCOLS  16384
#define NT     512
#define V4     (NCOLS / 4 / NT)     // 8 float4 per thread
#define KSEL   256
#define CAP    2048
#define NW     (NT / 32)
#define RST    8
#define FTZ    0.70f                // fixed pre-threshold (z units)

__global__ __launch_bounds__(NT, 3)
void entmax_topk_kernel(const float* __restrict__ logits,
                        float* __restrict__ out_w,
                        float* __restrict__ out_cnt)
{
    extern __shared__ float smbuf[];
    float* zs   = smbuf;            // NCOLS floats: z = 0.5*logit (per-thread spill)
    float* cand = smbuf + NCOLS;    // CAP floats

    __shared__ float s_f[NW];
    __shared__ int   s_i[NW];
    __shared__ float s_tau, s_th, s_inv;
    __shared__ int   s_useGe;

    const int tid  = threadIdx.x;
    const int lane = tid & 31;
    const int wid  = tid >> 5;
    const int row  = blockIdx.x;

    const float4* src = reinterpret_cast<const float4*>(logits) + (size_t)row * (NCOLS / 4);
    float4*       dst = reinterpret_cast<float4*>(out_w)        + (size_t)row * (NCOLS / 4);
    float4*       zs4 = reinterpret_cast<float4*>(zs);

    // ---- Pass A: ONE global sweep = smem row + max + fixed-threshold stash ----
    float stash[RST];
    int   lc = 0;
    float lmax = -INFINITY;
    #pragma unroll
    for (int j = 0; j < V4; ++j) {
        const int i = tid + j * NT;
        float4 t = __ldcs(&src[i]);
        t.x *= 0.5f; t.y *= 0.5f; t.z *= 0.5f; t.w *= 0.5f;
        zs4[i] = t;
        lmax = fmaxf(lmax, fmaxf(fmaxf(t.x, t.y), fmaxf(t.z, t.w)));
        if (t.x > FTZ) { if (lc < RST) stash[lc] = t.x; ++lc; }
        if (t.y > FTZ) { if (lc < RST) stash[lc] = t.y; ++lc; }
        if (t.z > FTZ) { if (lc < RST) stash[lc] = t.z; ++lc; }
        if (t.w > FTZ) { if (lc < RST) stash[lc] = t.w; ++lc; }
    }
    #pragma unroll
    for (int o = 16; o; o >>= 1) lmax = fmaxf(lmax, __shfl_xor_sync(0xffffffffu, lmax, o));
    if (lane == 0) s_f[wid] = lmax;
    __syncthreads();                                 // barrier 1
    float zmax;
    {
        float m = (lane < NW) ? s_f[lane] : -INFINITY;
        #pragma unroll
        for (int o = 8; o; o >>= 1) m = fmaxf(m, __shfl_xor_sync(0xffffffffu, m, o));
        zmax = __shfl_sync(0xffffffffu, m, 0);
    }
    const float cutoff = zmax - 1.0f;                // rigorous lower bound on tau
    // stash valid iff candidates {z > cutoff} ⊆ {z > FTZ} and no overflow
    const bool useStash = (cutoff >= FTZ) && (lc <= RST);

    // ---- count true candidates (stash, or own smem elements — on-SM fallback) ----
    int lcf = 0;
    if (useStash) {
        #pragma unroll
        for (int k = 0; k < RST; ++k) lcf += (k < lc && stash[k] > cutoff);
    } else {
        #pragma unroll
        for (int j = 0; j < V4; ++j) {
            float4 t = zs4[tid + j * NT];            // own data, conflict-free
            lcf += (t.x > cutoff) + (t.y > cutoff) + (t.z > cutoff) + (t.w > cutoff);
        }
    }
    // deterministic exclusive scan
    int inc = lcf;
    #pragma unroll
    for (int o = 1; o < 32; o <<= 1) {
        int t = __shfl_up_sync(0xffffffffu, inc, o);
        if (lane >= o) inc += t;
    }
    if (lane == 31) s_i[wid] = inc;
    __syncthreads();                                 // barrier 2
    int wbase, cn;
    {
        int a = (lane < NW) ? s_i[lane] : 0;
        int sc = a;
        #pragma unroll
        for (int o = 1; o < NW; o <<= 1) {
            int u = __shfl_up_sync(0xffffffffu, sc, o);
            if (lane >= o) sc += u;
        }
        cn    = __shfl_sync(0xffffffffu, sc, NW - 1);
        wbase = __shfl_sync(0xffffffffu, sc - a, wid);
    }
    const bool useCand = (cn <= CAP);
    if (useCand && lcf > 0) {
        int o = wbase + (inc - lcf);
        if (useStash) {
            #pragma unroll
            for (int k = 0; k < RST; ++k)
                if (k < lc && stash[k] > cutoff) cand[o++] = stash[k];
        } else {
            #pragma unroll
            for (int j = 0; j < V4; ++j) {
                float4 t = zs4[tid + j * NT];
                if (t.x > cutoff) cand[o++] = t.x;
                if (t.y > cutoff) cand[o++] = t.y;
                if (t.z > cutoff) cand[o++] = t.z;
                if (t.w > cutoff) cand[o++] = t.w;
            }
        }
    }
    __syncthreads();                                 // barrier 3

    // ---- warp 0: solve tau/th/inv AND num_selected ----
    if (wid == 0) {
        const float* cb = useCand ? cand : zs;       // overflow: whole smem row
        const int    n  = useCand ? cn : NCOLS;
        float tau = cutoff, th, inv;
        int useGe = 0, sel = 0;

        if (n <= 256) {
            float rv[8];
            #pragma unroll
            for (int r = 0; r < 8; ++r) {
                int idx = r * 32 + lane;
                rv[r] = (idx < n) ? cb[idx] : -1e30f;
            }
            float gfin = 0.f;
            for (int it = 0; it < 24; ++it) {
                float g = 0.f, gp = 0.f;
                #pragma unroll
                for (int r = 0; r < 8; ++r) {
                    float d = rv[r] - tau;
                    if (d > 0.f) { g = fmaf(d, d, g); gp += d; }
                }
                #pragma unroll
                for (int o = 16; o; o >>= 1) {
                    g  += __shfl_xor_sync(0xffffffffu, g,  o);
                    gp += __shfl_xor_sync(0xffffffffu, gp, o);
                }
                gfin = g;
                g -= 1.0f;
                if (gp <= 0.f) break;
                float step = g / (2.0f * gp);
                tau += step;
                if (step < 1e-7f) break;
            }
            int S = 0;
            #pragma unroll
            for (int r = 0; r < 8; ++r) S += (rv[r] > tau) ? 1 : 0;
            #pragma unroll
            for (int o = 16; o; o >>= 1) S += __shfl_xor_sync(0xffffffffu, S, o);

            th = tau;
            float ssum = gfin;
            if (S > KSEL) {                          // rare: bisect K-th largest z
                useGe = 1;
                float lo = tau, hi = zmax;
                for (int it = 0; it < 48; ++it) {
                    float mid = 0.5f * (lo + hi);
                    int c = 0;
                    #pragma unroll
                    for (int r = 0; r < 8; ++r) c += (rv[r] >= mid) ? 1 : 0;
                    #pragma unroll
                    for (int o = 16; o; o >>= 1) c += __shfl_xor_sync(0xffffffffu, c, o);
                    if (c >= KSEL) lo = mid; else hi = mid;
                }
                th = lo;
                ssum = 0.f;
                #pragma unroll
                for (int r = 0; r < 8; ++r) {
                    float z = rv[r], d = z - tau;
                    if (z >= th && d > 0.f) ssum = fmaf(d, d, ssum);
                }
                #pragma unroll
                for (int o = 16; o; o >>= 1) ssum += __shfl_xor_sync(0xffffffffu, ssum, o);
            }
            inv = 1.0f / (ssum + 1e-8f);
            #pragma unroll
            for (int r = 0; r < 8; ++r) {            // exact num_selected
                float z = rv[r], d = z - tau;
                bool keep = useGe ? (z >= th && d > 0.f) : (d > 0.f);
                float w = keep ? d * d * inv : 0.f;
                sel += (w > 1e-6f);
            }
        } else {
            float gfin = 0.f;
            for (int it = 0; it < 24; ++it) {
                float g = 0.f, gp = 0.f;
                for (int i = lane; i < n; i += 32) {
                    float d = cb[i] - tau;
                    if (d > 0.f) { g = fmaf(d, d, g); gp += d; }
                }
                #pragma unroll
                for (int o = 16; o; o >>= 1) {
                    g  += __shfl_xor_sync(0xffffffffu, g,  o);
                    gp += __shfl_xor_sync(0xffffffffu, gp, o);
                }
                gfin = g;
                g -= 1.0f;
                if (gp <= 0.f) break;
                float step = g / (2.0f * gp);
                tau += step;
                if (step < 1e-7f) break;
            }
            int S = 0;
            for (int i = lane; i < n; i += 32) S += (cb[i] > tau) ? 1 : 0;
            #pragma unroll
            for (int o = 16; o; o >>= 1) S += __shfl_xor_sync(0xffffffffu, S, o);

            th = tau;
            float ssum = gfin;
            if (S > KSEL) {
                useGe = 1;
                float lo = tau, hi = zmax;
                for (int it = 0; it < 48; ++it) {
                    float mid = 0.5f * (lo + hi);
                    int c = 0;
                    for (int i = lane; i < n; i += 32) c += (cb[i] >= mid) ? 1 : 0;
                    #pragma unroll
                    for (int o = 16; o; o >>= 1) c += __shfl_xor_sync(0xffffffffu, c, o);
                    if (c >= KSEL) lo = mid; else hi = mid;
                }
                th = lo;
                ssum = 0.f;
                for (int i = lane; i < n; i += 32) {
                    float z = cb[i], d = z - tau;
                    if (z >= th && d > 0.f) ssum = fmaf(d, d, ssum);
                }
                #pragma unroll
                for (int o = 16; o; o >>= 1) ssum += __shfl_xor_sync(0xffffffffu, ssum, o);
            }
            inv = 1.0f / (ssum + 1e-8f);
            for (int i = lane; i < n; i += 32) {
                float z = cb[i], d = z - tau;
                bool keep = useGe ? (z >= th && d > 0.f) : (d > 0.f);
                float w = keep ? d * d * inv : 0.f;
                sel += (w > 1e-6f);
            }
        }
        #pragma unroll
        for (int o = 16; o; o >>= 1) sel += __shfl_xor_sync(0xffffffffu, sel, o);
        if (lane == 0) {
            s_tau = tau; s_th = th; s_useGe = useGe; s_inv = inv;
            out_cnt[row] = (float)sel;
        }
    }
    __syncthreads();                                 // barrier 4 (last)

    const float tau = s_tau, th = s_th, inv = s_inv;
    const bool  useGe = (s_useGe != 0);

    // ---- Output: barrier-free (own smem elements -> weights -> __stcs) ----
    #pragma unroll
    for (int j = 0; j < V4; ++j) {
        float4 t = zs4[tid + j * NT];
        float4 w;
        {
            float z = t.x, d = z - tau;
            bool keep = useGe ? (z >= th && d > 0.f) : (d > 0.f);
            w.x = keep ? d * d * inv : 0.f;
        }
        {
            float z = t.y, d = z - tau;
            bool keep = useGe ? (z >= th && d > 0.f) : (d > 0.f);
            w.y = keep ? d * d * inv : 0.f;
        }
        {
            float z = t.z, d = z - tau;
            bool keep = useGe ? (z >= th && d > 0.f) : (d > 0.f);
            w.z = keep ? d * d * inv : 0.f;
        }
        {
            float z = t.w, d = z - tau;
            bool keep = useGe ? (z >= th && d > 0.f) : (d > 0.f);
            w.w = keep ? d * d * inv : 0.f;
        }
        __stcs(&dst[tid + j * NT], w);
    }
}

extern "C" void kernel_launch(void* const* d_in, const int* in_sizes, int n_in,
                              void* d_out, int out_size)
{
    const float* logits = (const float*)d_in[0];
    float* out = (float*)d_out;
    const int B = in_sizes[0] / NCOLS;

    const size_t smem = (size_t)(NCOLS + CAP) * sizeof(float);   // 73728 B
    cudaFuncSetAttribute(entmax_topk_kernel,
                         cudaFuncAttributeMaxDynamicSharedMemorySize, (int)smem);
    entmax_topk_kernel<<<B, NT, smem>>>(logits, out, out + (size_t)B * NCOLS);
}